// round 11
// baseline (speedup 1.0000x reference)
#include <cuda_runtime.h>

// EfConv: out[n, k*64+o] = b[o] + sum_{e: dst[e]==n} edge_feat[e,k] * z[src[e], o]
// where z = node_feat @ W^T.
//
// Pipeline:
//   0. zhist_kernel : z = nf @ W^T (64 nodes/block, f32x2 FFMA) + histogram
//   1. scan_kernel  : smem-resident scan (warp-shuffle hierarchy); re-zeros counts
//   2. build_kernel : scatter (src<<8) + ef rows into CSR order (8 edges/thr)
//   3. gather_kernel: warp-per-node; batch-resolve 32 edges into ZERO-PADDED
//                     smem; branch-free inner loop over 8-edge groups:
//                     2 LDS int4 offsets + 8 independent z LDG.64 (MLP=8),
//                     then per edge 2 LDS.128 + 2 dup movs + 8 FFMA2.
//                     Padding edges have off=0 (z row 0) and ef=0 -> add 0.

#define MAX_N 50000
#define MAX_E 800000

__device__ float g_z[MAX_N * 64];
__device__ int   g_counts[MAX_N];
__device__ int   g_offsets[MAX_N + 1];
__device__ int   g_cursor[MAX_N];
__device__ int   g_srcs[MAX_E];          // src<<8 (byte offset of z row)
__device__ float g_efs[(size_t)MAX_E * 8];

// ---------------------------------------------------------------------------
__device__ __forceinline__ void ffma2(unsigned long long& d,
                                      unsigned long long a,
                                      unsigned long long b) {
    asm("fma.rn.f32x2 %0, %1, %2, %0;" : "+l"(d) : "l"(a), "l"(b));
}
__device__ __forceinline__ unsigned long long dupf(float v) {
    unsigned long long r;
    asm("mov.b64 %0, {%1, %1};" : "=l"(r) : "r"(__float_as_uint(v)));
    return r;
}
__device__ __forceinline__ float2 unpack2(unsigned long long v) {
    unsigned int lo, hi;
    asm("mov.b64 {%0, %1}, %2;" : "=r"(lo), "=r"(hi) : "l"(v));
    return make_float2(__uint_as_float(lo), __uint_as_float(hi));
}

// ---------------------------------------------------------------------------
// z = nf @ W^T, 64 nodes/block, thread = 4 nodes x 2 out-pairs (f32x2).
// Plus grid-stride int4 histogram of dst.
// ---------------------------------------------------------------------------
__global__ __launch_bounds__(256)
void zhist_kernel(const float* __restrict__ nf,
                  const float* __restrict__ W,
                  const int* __restrict__ dst, int N, int E) {
    __shared__ float Ws[64 * 68];    // Ws[i*68+o] = W[o*64+i]
    __shared__ float nfs[64 * 64];
    int tid = threadIdx.x;

#pragma unroll
    for (int it = 0; it < 16; ++it) {
        int idx = it * 256 + tid;            // idx = o*64 + i
        int o = idx >> 6, i = idx & 63;
        Ws[i * 68 + o] = W[idx];
    }

    int nb = blockIdx.x * 64;
#pragma unroll
    for (int it = 0; it < 16; ++it) {
        int idx = it * 256 + tid;
        int n = nb + (idx >> 6);
        nfs[idx] = (n < N) ? nf[(size_t)n * 64 + (idx & 63)] : 0.0f;
    }

    int gs = gridDim.x * 256;
    int quads = (E + 3) >> 2;
    for (int u = blockIdx.x * 256 + tid; u < quads; u += gs) {
        int e4 = u * 4;
        if (e4 + 3 < E) {
            int4 d = *(const int4*)(dst + e4);
            atomicAdd(&g_counts[d.x], 1);
            atomicAdd(&g_counts[d.y], 1);
            atomicAdd(&g_counts[d.z], 1);
            atomicAdd(&g_counts[d.w], 1);
        } else {
            for (int e = e4; e < E; ++e) atomicAdd(&g_counts[dst[e]], 1);
        }
    }
    __syncthreads();

    int ng = tid >> 4;        // node group 0..15
    int ow = tid & 15;        // out quad 0..15
    unsigned long long accp[4][2];
#pragma unroll
    for (int j = 0; j < 4; ++j) { accp[j][0] = 0ull; accp[j][1] = 0ull; }

#pragma unroll 4
    for (int i = 0; i < 64; ++i) {
        ulonglong2 wp = *(const ulonglong2*)(Ws + i * 68 + ow * 4);
        unsigned long long a0 = dupf(nfs[(ng * 4 + 0) * 64 + i]);
        unsigned long long a1 = dupf(nfs[(ng * 4 + 1) * 64 + i]);
        unsigned long long a2 = dupf(nfs[(ng * 4 + 2) * 64 + i]);
        unsigned long long a3 = dupf(nfs[(ng * 4 + 3) * 64 + i]);
        ffma2(accp[0][0], wp.x, a0);  ffma2(accp[0][1], wp.y, a0);
        ffma2(accp[1][0], wp.x, a1);  ffma2(accp[1][1], wp.y, a1);
        ffma2(accp[2][0], wp.x, a2);  ffma2(accp[2][1], wp.y, a2);
        ffma2(accp[3][0], wp.x, a3);  ffma2(accp[3][1], wp.y, a3);
    }

#pragma unroll
    for (int j = 0; j < 4; ++j) {
        int n = nb + ng * 4 + j;
        if (n < N)
            *(ulonglong2*)(g_z + (size_t)n * 64 + ow * 4) =
                make_ulonglong2(accp[j][0], accp[j][1]);
    }
}

// ---------------------------------------------------------------------------
__global__ __launch_bounds__(1024)
void scan_kernel(int N) {
    extern __shared__ int ss[];
    int* s     = ss;          // [N]
    int* wsum  = ss + N;      // [32]
    int t    = threadIdx.x;
    int lane = t & 31;
    int wid  = t >> 5;
    int C = (N + 1023) >> 10;

    for (int i = t; i < N; i += 1024) {
        s[i] = g_counts[i];
        g_counts[i] = 0;
    }
    __syncthreads();

    int base = t * C;
    int sum = 0;
    for (int i = 0; i < C; ++i) {
        int n = base + i;
        if (n < N) sum += s[n];
    }

    int v = sum;
#pragma unroll
    for (int d = 1; d < 32; d <<= 1) {
        int u = __shfl_up_sync(0xffffffffu, v, d);
        if (lane >= d) v += u;
    }
    if (lane == 31) wsum[wid] = v;
    __syncthreads();

    if (wid == 0) {
        int wv = wsum[lane];
#pragma unroll
        for (int d = 1; d < 32; d <<= 1) {
            int u = __shfl_up_sync(0xffffffffu, wv, d);
            if (lane >= d) wv += u;
        }
        wsum[lane] = wv;
    }
    __syncthreads();

    int excl = v - sum + (wid > 0 ? wsum[wid - 1] : 0);
    int total = wsum[31];

    int run = excl;
    for (int i = 0; i < C; ++i) {
        int n = base + i;
        if (n < N) {
            int c = s[n];
            s[n] = run;
            run += c;
        }
    }
    __syncthreads();

    for (int i = t; i < N; i += 1024) {
        int o = s[i];
        g_offsets[i] = o;
        g_cursor[i]  = o;
    }
    if (t == 0) g_offsets[N] = total;
}

// ---------------------------------------------------------------------------
// Scatter src + ef rows into dst-sorted order. 8 edges/thread for MLP.
// ---------------------------------------------------------------------------
__global__ __launch_bounds__(256)
void build_kernel(const int* __restrict__ dst,
                  const int* __restrict__ src,
                  const float* __restrict__ ef, int E) {
    int t = blockIdx.x * 256 + threadIdx.x;
    int e8 = t * 8;
    if (e8 + 7 < E) {
        int4 d0 = *(const int4*)(dst + e8);
        int4 d1 = *(const int4*)(dst + e8 + 4);
        int4 s0 = *(const int4*)(src + e8);
        int4 s1 = *(const int4*)(src + e8 + 4);
        int p0 = atomicAdd(&g_cursor[d0.x], 1);
        int p1 = atomicAdd(&g_cursor[d0.y], 1);
        int p2 = atomicAdd(&g_cursor[d0.z], 1);
        int p3 = atomicAdd(&g_cursor[d0.w], 1);
        int p4 = atomicAdd(&g_cursor[d1.x], 1);
        int p5 = atomicAdd(&g_cursor[d1.y], 1);
        int p6 = atomicAdd(&g_cursor[d1.z], 1);
        int p7 = atomicAdd(&g_cursor[d1.w], 1);
        const float4* p = (const float4*)(ef + (size_t)e8 * 8);
        g_srcs[p0] = s0.x << 8; g_srcs[p1] = s0.y << 8;
        g_srcs[p2] = s0.z << 8; g_srcs[p3] = s0.w << 8;
        g_srcs[p4] = s1.x << 8; g_srcs[p5] = s1.y << 8;
        g_srcs[p6] = s1.z << 8; g_srcs[p7] = s1.w << 8;
        int pos[8] = {p0, p1, p2, p3, p4, p5, p6, p7};
#pragma unroll
        for (int j = 0; j < 8; ++j) {
            float4 a = p[j * 2];
            float4 b = p[j * 2 + 1];
            float4* q = (float4*)(g_efs + (size_t)pos[j] * 8);
            q[0] = a;
            q[1] = b;
        }
    } else {
        for (int e = e8; e < E; ++e) {
            int pp = atomicAdd(&g_cursor[dst[e]], 1);
            g_srcs[pp] = src[e] << 8;
            const float4* p = (const float4*)(ef + (size_t)e * 8);
            float4 a = p[0], b = p[1];
            float4* q = (float4*)(g_efs + (size_t)pp * 8);
            q[0] = a; q[1] = b;
        }
    }
}

// ---------------------------------------------------------------------------
// Warp per node. acc[kp] = (out[2kp][c0], out[2kp+1][c0]) packed f32x2,
// acc[4+kp] for c1, (c0,c1) = (2*lane, 2*lane+1).
// Per 32-edge batch: lane-parallel resolve into zero-padded smem.
// Inner loop: branch-free 8-edge groups, 8 z loads in flight (MLP=8).
// ---------------------------------------------------------------------------
__global__ __launch_bounds__(256)
void gather_kernel(const float* __restrict__ bias,
                   float* __restrict__ out, int N) {
    __shared__ __align__(16) float4 sA[8][32];
    __shared__ __align__(16) float4 sB[8][32];
    __shared__ __align__(16) int sOf[8][32];
    int wblk = threadIdx.x >> 5;
    int w    = (blockIdx.x * blockDim.x + threadIdx.x) >> 5;
    int lane = threadIdx.x & 31;
    if (w >= N) return;

    int start = g_offsets[w];
    int cnt   = g_offsets[w + 1] - start;

    float2 bv = ((const float2*)bias)[lane];
    unsigned long long acc[8];
#pragma unroll
    for (int kp = 0; kp < 4; ++kp) {
        acc[kp]     = dupf(bv.x);
        acc[4 + kp] = dupf(bv.y);
    }

    const char* zl = (const char*)g_z + lane * 8;

    for (int base = 0; base < cnt; base += 32) {
        int m = min(32, cnt - base);
        int idx = start + base + lane;
        int off = 0;
        float4 ea = make_float4(0.f, 0.f, 0.f, 0.f);
        float4 eb = make_float4(0.f, 0.f, 0.f, 0.f);
        if (lane < m) {
            off = g_srcs[idx];
            const float4* p = (const float4*)(g_efs + (size_t)idx * 8);
            ea = p[0];
            eb = p[1];
        }
        sOf[wblk][lane] = off;
        sA[wblk][lane] = ea;
        sB[wblk][lane] = eb;
        __syncwarp();

        int g8 = (m + 7) >> 3;
        for (int g = 0; g < g8; ++g) {
            int e0 = g * 8;
            int4 oa = *(const int4*)&sOf[wblk][e0];
            int4 ob = *(const int4*)&sOf[wblk][e0 + 4];
            float2 zz[8];
            zz[0] = *(const float2*)(zl + oa.x);
            zz[1] = *(const float2*)(zl + oa.y);
            zz[2] = *(const float2*)(zl + oa.z);
            zz[3] = *(const float2*)(zl + oa.w);
            zz[4] = *(const float2*)(zl + ob.x);
            zz[5] = *(const float2*)(zl + ob.y);
            zz[6] = *(const float2*)(zl + ob.z);
            zz[7] = *(const float2*)(zl + ob.w);

#pragma unroll
            for (int j = 0; j < 8; ++j) {
                ulonglong2 eA = *(const ulonglong2*)&sA[wblk][e0 + j];
                ulonglong2 eB = *(const ulonglong2*)&sB[wblk][e0 + j];
                unsigned long long zx = dupf(zz[j].x);
                unsigned long long zy = dupf(zz[j].y);
                ffma2(acc[0], eA.x, zx);  ffma2(acc[4], eA.x, zy);
                ffma2(acc[1], eA.y, zx);  ffma2(acc[5], eA.y, zy);
                ffma2(acc[2], eB.x, zx);  ffma2(acc[6], eB.x, zy);
                ffma2(acc[3], eB.y, zx);  ffma2(acc[7], eB.y, zy);
            }
        }
        __syncwarp();
    }

    float* op = out + (size_t)w * 512 + 2 * lane;
#pragma unroll
    for (int kp = 0; kp < 4; ++kp) {
        float2 lo = unpack2(acc[kp]);
        float2 hi = unpack2(acc[4 + kp]);
        *(float2*)(op + (2 * kp) * 64)     = make_float2(lo.x, hi.x);
        *(float2*)(op + (2 * kp + 1) * 64) = make_float2(lo.y, hi.y);
    }
}

// ---------------------------------------------------------------------------
extern "C" void kernel_launch(void* const* d_in, const int* in_sizes, int n_in,
                              void* d_out, int out_size) {
    const float* node_feat = (const float*)d_in[0];
    const float* edge_feat = (const float*)d_in[1];
    const float* W         = (const float*)d_in[2];
    const float* b         = (const float*)d_in[3];
    const int*   src       = (const int*)d_in[4];
    const int*   dst       = (const int*)d_in[5];
    float*       out       = (float*)d_out;

    int N = in_sizes[0] / 64;
    int E = in_sizes[4];

    size_t scan_smem = (size_t)(N + 32) * sizeof(int);
    cudaFuncSetAttribute(scan_kernel,
                         cudaFuncAttributeMaxDynamicSharedMemorySize,
                         (int)scan_smem);

    int zb = (N + 63) / 64;
    zhist_kernel<<<zb, 256>>>(node_feat, W, dst, N, E);
    scan_kernel<<<1, 1024, scan_smem>>>(N);
    build_kernel<<<((E + 7) / 8 + 255) / 256, 256>>>(dst, src, edge_feat, E);
    gather_kernel<<<(N * 32 + 255) / 256, 256>>>(b, out, N);
}